// round 3
// baseline (speedup 1.0000x reference)
#include <cuda_runtime.h>
#include <cstddef>

#define B_CONST 262144
#define E_CONST 100000
#define CYCLE 30
#define SDIM 64
#define TDIM 64
#define ROWDIM 128
#define BIN_CAP 96
#define READY_BIT 0x10000

// ---- static device scratch ----
__device__ int      g_bincnt[E_CONST];
__device__ unsigned g_binlist[(size_t)E_CONST * BIN_CAP];
__device__ int      g_flag[B_CONST];
// first visitor's te vectors: [s][0:64]=te_h(ent), [64:128]=te_t(ent)
__device__ float    g_tevec[(size_t)B_CONST * 128];
__device__ float    g_temporal[B_CONST];

__device__ __forceinline__ float2 ld2(const float* __restrict__ p) {
    return *reinterpret_cast<const float2*>(p);
}
__device__ __forceinline__ float2 ld2cg(const float* __restrict__ p) {
    float2 v;
    asm volatile("ld.global.cg.v2.f32 {%0,%1}, [%2];"
                 : "=f"(v.x), "=f"(v.y) : "l"(p));
    return v;
}
__device__ __forceinline__ void st2(float* __restrict__ p, float2 v) {
    *reinterpret_cast<float2*>(p) = v;
}

// ---------------- pass 0: zero counters + flags ----------------
__global__ void zero_kernel() {
    int i = blockIdx.x * blockDim.x + threadIdx.x;
    if (i < E_CONST) g_bincnt[i] = 0;
    if (i < B_CONST) g_flag[i] = 0;
}

// ---------------- pass 1: scatter items into entity bins ----------------
__global__ void scatter_kernel(const int* __restrict__ heads,
                               const int* __restrict__ tails) {
    int i = blockIdx.x * blockDim.x + threadIdx.x;   // item id in [0, 2B)
    if (i >= 2 * B_CONST) return;
    const int s = i >> 1;
    const int e = (i & 1) ? tails[s] : heads[s];
    int pos = atomicAdd(&g_bincnt[e], 1);
    if (pos < BIN_CAP)
        g_binlist[(size_t)e * BIN_CAP + pos] = (unsigned)i;
}

// ---------------- pass 2: per-entity te + rendezvous temporal dot ----------------
__global__ __launch_bounds__(256)
void te_kernel(const int*   __restrict__ rels,
               const int*   __restrict__ date_ids,
               const float* __restrict__ years,
               const float* __restrict__ months,
               const float* __restrict__ days,
               const float* __restrict__ rel_f,
               const float* __restrict__ rel_i,
               const float* __restrict__ stw,
               const float* __restrict__ rtc,
               const float* __restrict__ amps_h,
               const float* __restrict__ freq_h,
               const float* __restrict__ phi_h,
               const float* __restrict__ amps_t,
               const float* __restrict__ freq_t,
               const float* __restrict__ phi_t)
{
    const int gtid = blockIdx.x * blockDim.x + threadIdx.x;
    const int e    = gtid >> 5;               // one warp per entity bin
    if (e >= E_CONST) return;
    int n = g_bincnt[e];
    if (n <= 0) return;
    if (n > BIN_CAP) n = BIN_CAP;

    const int lane = threadIdx.x & 31;
    const int d2   = lane << 1;

    // gather this entity's 18 unique table rows ONCE
    float2 ah[3], fh[3], ph[3], at[3], ft[3], pt[3];
#pragma unroll
    for (int c = 0; c < 3; ++c) {
        const size_t off = ((size_t)c * E_CONST + (size_t)e) * TDIM + d2;
        ah[c] = ld2(amps_h + off);
        fh[c] = ld2(freq_h + off);
        ph[c] = ld2(phi_h  + off);
        at[c] = ld2(amps_t + off);
        ft[c] = ld2(freq_t + off);
        pt[c] = ld2(phi_t  + off);
    }

    const size_t binbase = (size_t)e * BIN_CAP;
    for (int j = 0; j < n; ++j) {
        const unsigned it = g_binlist[binbase + j];
        const int s    = (int)(it >> 1);
        const int role = (int)(it & 1);       // 0 = head visit, 1 = tail visit
        float tv[3];
        tv[0] = __ldg(years  + s);
        tv[1] = __ldg(months + s);
        tv[2] = __ldg(days   + s);

        // own te_h / te_t vectors (no shared window; added at the dot)
        float2 myH = make_float2(0.f, 0.f), myT = make_float2(0.f, 0.f);
#pragma unroll
        for (int c = 0; c < 3; ++c) {
            myH.x = fmaf(ah[c].x, __sinf(fmaf(fh[c].x, tv[c], ph[c].x)), myH.x);
            myH.y = fmaf(ah[c].y, __sinf(fmaf(fh[c].y, tv[c], ph[c].y)), myH.y);
            myT.x = fmaf(at[c].x, __sinf(fmaf(ft[c].x, tv[c], pt[c].x)), myT.x);
            myT.y = fmaf(at[c].y, __sinf(fmaf(ft[c].y, tv[c], pt[c].y)), myT.y);
        }

        int arr;
        if (lane == 0) arr = atomicAdd(&g_flag[s], 1);
        arr = __shfl_sync(0xFFFFFFFFu, arr, 0);

        float* slot = g_tevec + (size_t)s * 128 + d2;

        if ((arr & 0xFFFF) == 0) {
            // FIRST visitor: publish my vectors, then set READY
            st2(slot,      myH);
            st2(slot + 64, myT);
            __syncwarp();
            if (lane == 0) {
                __threadfence();
                atomicOr(&g_flag[s], READY_BIT);
            }
        } else {
            // SECOND visitor: wait for partner's publish, compute temporal dot
            if (!(arr & READY_BIT)) {
                if (lane == 0) {
                    while (!(atomicAdd(&g_flag[s], 0) & READY_BIT))
                        __nanosleep(20);
                }
                __syncwarp();
            }
            const float2 pH = ld2cg(slot);
            const float2 pT = ld2cg(slot + 64);

            // canonical head/tail assignment (bit-identical either visit order)
            float2 hH, hT, tH, tT;
            if (role == 0) { hH = myH; hT = myT; tH = pH; tT = pT; }
            else           { hH = pH;  hT = pT;  tH = myH; tT = myT; }

            const int r  = __ldg(rels + s);
            const int di = __ldg(date_ids + s);
            const float2 sw  = ld2(stw   + (size_t)(di / CYCLE) * TDIM + d2);
            const float2 rft = ld2(rel_f + (size_t)r * ROWDIM + SDIM + d2);
            const float2 rit = ld2(rel_i + (size_t)r * ROWDIM + SDIM + d2);
            const float2 tct = ld2(rtc   + (size_t)di * ROWDIM + SDIM + d2);

            const float r1tx = rft.x * (1.0f + tct.x), r1ty = rft.y * (1.0f + tct.y);
            const float r2tx = rit.x * (1.0f + tct.x), r2ty = rit.y * (1.0f + tct.y);

            const float h1x = hH.x + sw.x, h1y = hH.y + sw.y;
            const float t1x = tT.x + sw.x, t1y = tT.y + sw.y;
            const float h2x = tH.x + sw.x, h2y = tH.y + sw.y;
            const float t2x = hT.x + sw.x, t2y = hT.y + sw.y;

            float acc = 0.0f;
            acc = fmaf(h1x * r1tx, t1x, acc);
            acc = fmaf(h1y * r1ty, t1y, acc);
            acc = fmaf(h2x * r2tx, t2x, acc);
            acc = fmaf(h2y * r2ty, t2y, acc);

#pragma unroll
            for (int m = 16; m > 0; m >>= 1)
                acc += __shfl_xor_sync(0xFFFFFFFFu, acc, m);

            if (lane == 0)
                g_temporal[s] = acc;
        }
    }
}

// ---------------- pass 3: structural score + temporal scalar ----------------
__global__ __launch_bounds__(256)
void score_kernel(const int*   __restrict__ heads,
                  const int*   __restrict__ rels,
                  const int*   __restrict__ tails,
                  const int*   __restrict__ date_ids,
                  const float* __restrict__ ent_h,
                  const float* __restrict__ ent_t,
                  const float* __restrict__ rel_f,
                  const float* __restrict__ rel_i,
                  const float* __restrict__ rtc,
                  float* __restrict__ out)
{
    const int gtid = blockIdx.x * blockDim.x + threadIdx.x;
    const int w    = gtid >> 5;              // one warp per sample
    if (w >= B_CONST) return;
    const int lane = threadIdx.x & 31;
    const int d2   = lane << 1;

    const int h  = heads[w];
    const int r  = rels[w];
    const int t  = tails[w];
    const int di = date_ids[w];

    const float2 ehh = ld2(ent_h + (size_t)h * SDIM + d2);
    const float2 eht = ld2(ent_h + (size_t)t * SDIM + d2);
    const float2 ett = ld2(ent_t + (size_t)t * SDIM + d2);
    const float2 eth = ld2(ent_t + (size_t)h * SDIM + d2);
    const float2 rfs = ld2(rel_f + (size_t)r * ROWDIM + d2);
    const float2 ris = ld2(rel_i + (size_t)r * ROWDIM + d2);
    const float2 tcs = ld2(rtc   + (size_t)di * ROWDIM + d2);

    const float r1sx = rfs.x * (1.0f + tcs.x), r1sy = rfs.y * (1.0f + tcs.y);
    const float r2sx = ris.x * (1.0f + tcs.x), r2sy = ris.y * (1.0f + tcs.y);

    float acc = 0.0f;
    acc = fmaf(ehh.x * r1sx, ett.x, acc);
    acc = fmaf(ehh.y * r1sy, ett.y, acc);
    acc = fmaf(eht.x * r2sx, eth.x, acc);
    acc = fmaf(eht.y * r2sy, eth.y, acc);

#pragma unroll
    for (int m = 16; m > 0; m >>= 1)
        acc += __shfl_xor_sync(0xFFFFFFFFu, acc, m);

    if (lane == 0)
        out[w] = 0.5f * (acc + g_temporal[w]);
}

extern "C" void kernel_launch(void* const* d_in, const int* in_sizes, int n_in,
                              void* d_out, int out_size)
{
    const int*   heads    = (const int*)  d_in[0];
    const int*   rels     = (const int*)  d_in[1];
    const int*   tails    = (const int*)  d_in[2];
    const float* years    = (const float*)d_in[3];
    const float* months   = (const float*)d_in[4];
    const float* days     = (const float*)d_in[5];
    const int*   date_ids = (const int*)  d_in[6];
    const float* ent_h    = (const float*)d_in[7];
    const float* ent_t    = (const float*)d_in[8];
    const float* rel_f    = (const float*)d_in[9];
    const float* rel_i    = (const float*)d_in[10];
    const float* stw      = (const float*)d_in[11];
    const float* rtc      = (const float*)d_in[12];
    const float* amps_h   = (const float*)d_in[13];
    const float* freq_h   = (const float*)d_in[14];
    const float* phi_h    = (const float*)d_in[15];
    const float* amps_t   = (const float*)d_in[16];
    const float* freq_t   = (const float*)d_in[17];
    const float* phi_t    = (const float*)d_in[18];

    zero_kernel<<<(B_CONST + 255) / 256, 256>>>();

    scatter_kernel<<<(2 * B_CONST + 255) / 256, 256>>>(heads, tails);

    te_kernel<<<(E_CONST * 32 + 255) / 256, 256>>>(
        rels, date_ids, years, months, days,
        rel_f, rel_i, stw, rtc,
        amps_h, freq_h, phi_h, amps_t, freq_t, phi_t);

    score_kernel<<<(B_CONST * 32 + 255) / 256, 256>>>(
        heads, rels, tails, date_ids,
        ent_h, ent_t, rel_f, rel_i, rtc,
        (float*)d_out);
}

// round 4
// speedup vs baseline: 1.0413x; 1.0413x over previous
#include <cuda_runtime.h>
#include <cstddef>

#define B_CONST 262144
#define E_CONST 100000
#define CYCLE 30
#define SDIM 64
#define TDIM 64
#define ROWDIM 128
#define BIN_CAP 96

// ---- static device scratch ----
__device__ int    g_bincnt[E_CONST];
__device__ float4 g_binrec[(size_t)E_CONST * BIN_CAP];   // {y, m, d, item-as-float}
__device__ int    g_flag[B_CONST];
// per-sample, per-role te pair: [s][role][0:64]=te_h, [64:128]=te_t
__device__ float  g_tevec[(size_t)B_CONST * 256];
__device__ float  g_temporal[B_CONST];

__device__ __forceinline__ float2 ld2(const float* __restrict__ p) {
    return *reinterpret_cast<const float2*>(p);
}
__device__ __forceinline__ float2 ld2cg(const float* __restrict__ p) {
    float2 v;
    asm volatile("ld.global.cg.v2.f32 {%0,%1}, [%2];"
                 : "=f"(v.x), "=f"(v.y) : "l"(p));
    return v;
}
__device__ __forceinline__ void st2(float* __restrict__ p, float2 v) {
    *reinterpret_cast<float2*>(p) = v;
}

// ---------------- pass 0: zero counters + flags ----------------
__global__ void zero_kernel() {
    int i = blockIdx.x * blockDim.x + threadIdx.x;
    if (i < E_CONST) g_bincnt[i] = 0;
    if (i < B_CONST) { g_flag[i] = 0; g_temporal[i] = 0.0f; }
}

// ---------------- pass 1: scatter packed items into entity bins ----------------
__global__ void scatter_kernel(const int*   __restrict__ heads,
                               const int*   __restrict__ tails,
                               const float* __restrict__ years,
                               const float* __restrict__ months,
                               const float* __restrict__ days) {
    int i = blockIdx.x * blockDim.x + threadIdx.x;   // item id in [0, 2B)
    if (i >= 2 * B_CONST) return;
    const int s = i >> 1;
    const int e = (i & 1) ? tails[s] : heads[s];
    int pos = atomicAdd(&g_bincnt[e], 1);
    if (pos < BIN_CAP) {
        float4 rec;
        rec.x = years[s];
        rec.y = months[s];
        rec.z = days[s];
        rec.w = __int_as_float(i);
        g_binrec[(size_t)e * BIN_CAP + pos] = rec;
    }
}

// ---------------- pass 2: per-entity te + NON-BLOCKING rendezvous dot ----------------
__global__ __launch_bounds__(256)
void te_kernel(const int*   __restrict__ rels,
               const int*   __restrict__ date_ids,
               const float* __restrict__ rel_f,
               const float* __restrict__ rel_i,
               const float* __restrict__ stw,
               const float* __restrict__ rtc,
               const float* __restrict__ amps_h,
               const float* __restrict__ freq_h,
               const float* __restrict__ phi_h,
               const float* __restrict__ amps_t,
               const float* __restrict__ freq_t,
               const float* __restrict__ phi_t)
{
    const int gtid = blockIdx.x * blockDim.x + threadIdx.x;
    const int e    = gtid >> 5;               // one warp per entity bin
    if (e >= E_CONST) return;
    int n = g_bincnt[e];
    if (n <= 0) return;
    if (n > BIN_CAP) n = BIN_CAP;

    const int lane = threadIdx.x & 31;
    const int d2   = lane << 1;

    // gather this entity's 18 unique table rows ONCE
    float2 ah[3], fh[3], ph[3], at[3], ft[3], pt[3];
#pragma unroll
    for (int c = 0; c < 3; ++c) {
        const size_t off = ((size_t)c * E_CONST + (size_t)e) * TDIM + d2;
        ah[c] = ld2(amps_h + off);
        fh[c] = ld2(freq_h + off);
        ph[c] = ld2(phi_h  + off);
        at[c] = ld2(amps_t + off);
        ft[c] = ld2(freq_t + off);
        pt[c] = ld2(phi_t  + off);
    }

    const size_t binbase = (size_t)e * BIN_CAP;
    for (int j = 0; j < n; ++j) {
        const float4 rec = g_binrec[binbase + j];
        const int it   = __float_as_int(rec.w);
        const int s    = it >> 1;
        const int role = it & 1;              // 0 = head visit, 1 = tail visit
        const float tv0 = rec.x, tv1 = rec.y, tv2 = rec.z;

        // my te_h / te_t (no shared window; added at the dot)
        float2 myH = make_float2(0.f, 0.f), myT = make_float2(0.f, 0.f);
        {
            myH.x = fmaf(ah[0].x, __sinf(fmaf(fh[0].x, tv0, ph[0].x)), myH.x);
            myH.y = fmaf(ah[0].y, __sinf(fmaf(fh[0].y, tv0, ph[0].y)), myH.y);
            myT.x = fmaf(at[0].x, __sinf(fmaf(ft[0].x, tv0, pt[0].x)), myT.x);
            myT.y = fmaf(at[0].y, __sinf(fmaf(ft[0].y, tv0, pt[0].y)), myT.y);
            myH.x = fmaf(ah[1].x, __sinf(fmaf(fh[1].x, tv1, ph[1].x)), myH.x);
            myH.y = fmaf(ah[1].y, __sinf(fmaf(fh[1].y, tv1, ph[1].y)), myH.y);
            myT.x = fmaf(at[1].x, __sinf(fmaf(ft[1].x, tv1, pt[1].x)), myT.x);
            myT.y = fmaf(at[1].y, __sinf(fmaf(ft[1].y, tv1, pt[1].y)), myT.y);
            myH.x = fmaf(ah[2].x, __sinf(fmaf(fh[2].x, tv2, ph[2].x)), myH.x);
            myH.y = fmaf(ah[2].y, __sinf(fmaf(fh[2].y, tv2, ph[2].y)), myH.y);
            myT.x = fmaf(at[2].x, __sinf(fmaf(ft[2].x, tv2, pt[2].x)), myT.x);
            myT.y = fmaf(at[2].y, __sinf(fmaf(ft[2].y, tv2, pt[2].y)), myT.y);
        }

        // ALWAYS publish to my role slot, fence, then arrive. Never wait.
        float* myslot = g_tevec + ((size_t)s * 2 + role) * 128 + d2;
        st2(myslot,      myH);
        st2(myslot + 64, myT);
        __threadfence();          // each lane fences its own stores
        __syncwarp();

        int arr;
        if (lane == 0) arr = atomicAdd(&g_flag[s], 1);
        arr = __shfl_sync(0xFFFFFFFFu, arr, 0);

        if (arr == 1) {
            // I'm temporally second: partner's stores are fenced & published.
            const float* pslot = g_tevec + ((size_t)s * 2 + (role ^ 1)) * 128 + d2;
            const float2 pH = ld2cg(pslot);
            const float2 pT = ld2cg(pslot + 64);

            // canonical head/tail assignment (identical either visit order)
            float2 hH, hT, tH, tT;
            if (role == 0) { hH = myH; hT = myT; tH = pH;  tT = pT;  }
            else           { hH = pH;  hT = pT;  tH = myH; tT = myT; }

            const int r  = __ldg(rels + s);
            const int di = __ldg(date_ids + s);
            const float2 sw  = ld2(stw   + (size_t)(di / CYCLE) * TDIM + d2);
            const float2 rft = ld2(rel_f + (size_t)r * ROWDIM + SDIM + d2);
            const float2 rit = ld2(rel_i + (size_t)r * ROWDIM + SDIM + d2);
            const float2 tct = ld2(rtc   + (size_t)di * ROWDIM + SDIM + d2);

            const float r1tx = rft.x * (1.0f + tct.x), r1ty = rft.y * (1.0f + tct.y);
            const float r2tx = rit.x * (1.0f + tct.x), r2ty = rit.y * (1.0f + tct.y);

            const float h1x = hH.x + sw.x, h1y = hH.y + sw.y;
            const float t1x = tT.x + sw.x, t1y = tT.y + sw.y;
            const float h2x = tH.x + sw.x, h2y = tH.y + sw.y;
            const float t2x = hT.x + sw.x, t2y = hT.y + sw.y;

            float acc = 0.0f;
            acc = fmaf(h1x * r1tx, t1x, acc);
            acc = fmaf(h1y * r1ty, t1y, acc);
            acc = fmaf(h2x * r2tx, t2x, acc);
            acc = fmaf(h2y * r2ty, t2y, acc);

#pragma unroll
            for (int m = 16; m > 0; m >>= 1)
                acc += __shfl_xor_sync(0xFFFFFFFFu, acc, m);

            if (lane == 0)
                g_temporal[s] = acc;
        }
    }
}

// ---------------- pass 3: structural score + temporal scalar ----------------
__global__ __launch_bounds__(256)
void score_kernel(const int*   __restrict__ heads,
                  const int*   __restrict__ rels,
                  const int*   __restrict__ tails,
                  const int*   __restrict__ date_ids,
                  const float* __restrict__ ent_h,
                  const float* __restrict__ ent_t,
                  const float* __restrict__ rel_f,
                  const float* __restrict__ rel_i,
                  const float* __restrict__ rtc,
                  float* __restrict__ out)
{
    const int gtid = blockIdx.x * blockDim.x + threadIdx.x;
    const int w    = gtid >> 5;              // one warp per sample
    if (w >= B_CONST) return;
    const int lane = threadIdx.x & 31;
    const int d2   = lane << 1;

    const int h  = heads[w];
    const int r  = rels[w];
    const int t  = tails[w];
    const int di = date_ids[w];

    const float2 ehh = ld2(ent_h + (size_t)h * SDIM + d2);
    const float2 eht = ld2(ent_h + (size_t)t * SDIM + d2);
    const float2 ett = ld2(ent_t + (size_t)t * SDIM + d2);
    const float2 eth = ld2(ent_t + (size_t)h * SDIM + d2);
    const float2 rfs = ld2(rel_f + (size_t)r * ROWDIM + d2);
    const float2 ris = ld2(rel_i + (size_t)r * ROWDIM + d2);
    const float2 tcs = ld2(rtc   + (size_t)di * ROWDIM + d2);

    const float r1sx = rfs.x * (1.0f + tcs.x), r1sy = rfs.y * (1.0f + tcs.y);
    const float r2sx = ris.x * (1.0f + tcs.x), r2sy = ris.y * (1.0f + tcs.y);

    float acc = 0.0f;
    acc = fmaf(ehh.x * r1sx, ett.x, acc);
    acc = fmaf(ehh.y * r1sy, ett.y, acc);
    acc = fmaf(eht.x * r2sx, eth.x, acc);
    acc = fmaf(eht.y * r2sy, eth.y, acc);

#pragma unroll
    for (int m = 16; m > 0; m >>= 1)
        acc += __shfl_xor_sync(0xFFFFFFFFu, acc, m);

    if (lane == 0)
        out[w] = 0.5f * (acc + g_temporal[w]);
}

extern "C" void kernel_launch(void* const* d_in, const int* in_sizes, int n_in,
                              void* d_out, int out_size)
{
    const int*   heads    = (const int*)  d_in[0];
    const int*   rels     = (const int*)  d_in[1];
    const int*   tails    = (const int*)  d_in[2];
    const float* years    = (const float*)d_in[3];
    const float* months   = (const float*)d_in[4];
    const float* days     = (const float*)d_in[5];
    const int*   date_ids = (const int*)  d_in[6];
    const float* ent_h    = (const float*)d_in[7];
    const float* ent_t    = (const float*)d_in[8];
    const float* rel_f    = (const float*)d_in[9];
    const float* rel_i    = (const float*)d_in[10];
    const float* stw      = (const float*)d_in[11];
    const float* rtc      = (const float*)d_in[12];
    const float* amps_h   = (const float*)d_in[13];
    const float* freq_h   = (const float*)d_in[14];
    const float* phi_h    = (const float*)d_in[15];
    const float* amps_t   = (const float*)d_in[16];
    const float* freq_t   = (const float*)d_in[17];
    const float* phi_t    = (const float*)d_in[18];

    zero_kernel<<<(B_CONST + 255) / 256, 256>>>();

    scatter_kernel<<<(2 * B_CONST + 255) / 256, 256>>>(
        heads, tails, years, months, days);

    te_kernel<<<(E_CONST * 32 + 255) / 256, 256>>>(
        rels, date_ids,
        rel_f, rel_i, stw, rtc,
        amps_h, freq_h, phi_h, amps_t, freq_t, phi_t);

    score_kernel<<<(B_CONST * 32 + 255) / 256, 256>>>(
        heads, rels, tails, date_ids,
        ent_h, ent_t, rel_f, rel_i, rtc,
        (float*)d_out);
}

// round 5
// speedup vs baseline: 2.0161x; 1.9361x over previous
#include <cuda_runtime.h>
#include <cstddef>

#define B_CONST 262144
#define E_CONST 100000
#define CYCLE 30
#define SDIM 64
#define TDIM 64
#define ROWDIM 128
#define BIN_CAP 96

// ---- static device scratch ----
__device__ int    g_bincnt[E_CONST];
__device__ float4 g_binrec[(size_t)E_CONST * BIN_CAP];  // {y, m, d, item-as-int}
// te scratch: [sample][role*2 + vec][64]  (role0: head entity, role1: tail entity)
__device__ float  g_te[(size_t)B_CONST * 4 * 64];

__device__ __forceinline__ float2 ld2(const float* __restrict__ p) {
    return *reinterpret_cast<const float2*>(p);
}
__device__ __forceinline__ float4 ld4(const float* __restrict__ p) {
    return *reinterpret_cast<const float4*>(p);
}
__device__ __forceinline__ float4 ld4cs(const float* __restrict__ p) {
    float4 v;
    asm volatile("ld.global.cs.v4.f32 {%0,%1,%2,%3}, [%4];"
                 : "=f"(v.x), "=f"(v.y), "=f"(v.z), "=f"(v.w) : "l"(p));
    return v;
}
__device__ __forceinline__ void st2cs(float* __restrict__ p, float2 v) {
    asm volatile("st.global.cs.v2.f32 [%0], {%1,%2};"
                 :: "l"(p), "f"(v.x), "f"(v.y) : "memory");
}

// ---------------- pass 0: zero bin counters ----------------
__global__ void zero_kernel() {
    int i = blockIdx.x * blockDim.x + threadIdx.x;
    if (i < E_CONST) g_bincnt[i] = 0;
}

// ---------------- pass 1: scatter packed items into entity bins ----------------
__global__ void scatter_kernel(const int*   __restrict__ heads,
                               const int*   __restrict__ tails,
                               const float* __restrict__ years,
                               const float* __restrict__ months,
                               const float* __restrict__ days) {
    int i = blockIdx.x * blockDim.x + threadIdx.x;   // item id in [0, 2B)
    if (i >= 2 * B_CONST) return;
    const int s = i >> 1;
    const int e = (i & 1) ? tails[s] : heads[s];
    int pos = atomicAdd(&g_bincnt[e], 1);
    if (pos < BIN_CAP) {
        float4 rec;
        rec.x = years[s];
        rec.y = months[s];
        rec.z = days[s];
        rec.w = __int_as_float(i);
        g_binrec[(size_t)e * BIN_CAP + pos] = rec;
    }
}

// ---------------- pass 2: per-entity gather-once, emit te per item ----------------
__global__ __launch_bounds__(256)
void te_kernel(const float* __restrict__ amps_h,
               const float* __restrict__ freq_h,
               const float* __restrict__ phi_h,
               const float* __restrict__ amps_t,
               const float* __restrict__ freq_t,
               const float* __restrict__ phi_t)
{
    const int gtid = blockIdx.x * blockDim.x + threadIdx.x;
    const int e    = gtid >> 5;               // one warp per entity bin
    if (e >= E_CONST) return;
    int n = g_bincnt[e];
    if (n <= 0) return;
    if (n > BIN_CAP) n = BIN_CAP;

    const int lane = threadIdx.x & 31;
    const int d2   = lane << 1;

    // gather this entity's 18 unique table rows ONCE into registers
    float2 ah[3], fh[3], ph[3], at[3], ft[3], pt[3];
#pragma unroll
    for (int c = 0; c < 3; ++c) {
        const size_t off = ((size_t)c * E_CONST + (size_t)e) * TDIM + d2;
        ah[c] = ld2(amps_h + off);
        fh[c] = ld2(freq_h + off);
        ph[c] = ld2(phi_h  + off);
        at[c] = ld2(amps_t + off);
        ft[c] = ld2(freq_t + off);
        pt[c] = ld2(phi_t  + off);
    }

    const size_t binbase = (size_t)e * BIN_CAP;
    for (int j = 0; j < n; ++j) {
        const float4 rec = g_binrec[binbase + j];
        const int it   = __float_as_int(rec.w);
        const int s    = it >> 1;
        const int role = it & 1;
        const float tv0 = rec.x, tv1 = rec.y, tv2 = rec.z;

        float hx = 0.f, hy = 0.f, tx = 0.f, ty = 0.f;
        hx = fmaf(ah[0].x, __sinf(fmaf(fh[0].x, tv0, ph[0].x)), hx);
        hy = fmaf(ah[0].y, __sinf(fmaf(fh[0].y, tv0, ph[0].y)), hy);
        tx = fmaf(at[0].x, __sinf(fmaf(ft[0].x, tv0, pt[0].x)), tx);
        ty = fmaf(at[0].y, __sinf(fmaf(ft[0].y, tv0, pt[0].y)), ty);
        hx = fmaf(ah[1].x, __sinf(fmaf(fh[1].x, tv1, ph[1].x)), hx);
        hy = fmaf(ah[1].y, __sinf(fmaf(fh[1].y, tv1, ph[1].y)), hy);
        tx = fmaf(at[1].x, __sinf(fmaf(ft[1].x, tv1, pt[1].x)), tx);
        ty = fmaf(at[1].y, __sinf(fmaf(ft[1].y, tv1, pt[1].y)), ty);
        hx = fmaf(ah[2].x, __sinf(fmaf(fh[2].x, tv2, ph[2].x)), hx);
        hy = fmaf(ah[2].y, __sinf(fmaf(fh[2].y, tv2, ph[2].y)), hy);
        tx = fmaf(at[2].x, __sinf(fmaf(ft[2].x, tv2, pt[2].x)), tx);
        ty = fmaf(at[2].y, __sinf(fmaf(ft[2].y, tv2, pt[2].y)), ty);

        float* base = g_te + ((size_t)s * 4 + (size_t)role * 2) * 64 + d2;
        st2cs(base,      make_float2(hx, hy));   // te_h(entity)
        st2cs(base + 64, make_float2(tx, ty));   // te_t(entity)
    }
}

// ---------------- pass 3: score, 2 samples per warp, float4 lanes ----------------
__global__ __launch_bounds__(256)
void score_kernel(const int*   __restrict__ heads,
                  const int*   __restrict__ rels,
                  const int*   __restrict__ tails,
                  const int*   __restrict__ date_ids,
                  const float* __restrict__ ent_h,
                  const float* __restrict__ ent_t,
                  const float* __restrict__ rel_f,
                  const float* __restrict__ rel_i,
                  const float* __restrict__ stw,
                  const float* __restrict__ rtc,
                  float* __restrict__ out)
{
    const int gtid = blockIdx.x * blockDim.x + threadIdx.x;
    const int w2   = gtid >> 5;                 // warp id: 2 samples per warp
    const int lane = threadIdx.x & 31;
    const int w    = w2 * 2 + (lane >> 4);      // this half-warp's sample
    if (w >= B_CONST) return;
    const int q  = lane & 15;
    const int d4 = q << 2;                       // 4 dims per lane

    const int h  = heads[w];
    const int r  = rels[w];
    const int t  = tails[w];
    const int di = date_ids[w];

    // te scratch (stream, evict-first so ent/rel/rtc stay in L2)
    const float* tb = g_te + (size_t)w * 256 + d4;
    const float4 teHh = ld4cs(tb);
    const float4 teTh = ld4cs(tb + 64);
    const float4 teHt = ld4cs(tb + 128);
    const float4 teTt = ld4cs(tb + 192);

    const float4 sw  = ld4(stw + (size_t)(di / CYCLE) * TDIM + d4);
    const float4 ehh = ld4(ent_h + (size_t)h * SDIM + d4);
    const float4 eht = ld4(ent_h + (size_t)t * SDIM + d4);
    const float4 ett = ld4(ent_t + (size_t)t * SDIM + d4);
    const float4 eth = ld4(ent_t + (size_t)h * SDIM + d4);
    const float4 rfs = ld4(rel_f + (size_t)r * ROWDIM + d4);
    const float4 rft = ld4(rel_f + (size_t)r * ROWDIM + SDIM + d4);
    const float4 ris = ld4(rel_i + (size_t)r * ROWDIM + d4);
    const float4 rit = ld4(rel_i + (size_t)r * ROWDIM + SDIM + d4);
    const float4 tcs = ld4(rtc   + (size_t)di * ROWDIM + d4);
    const float4 tct = ld4(rtc   + (size_t)di * ROWDIM + SDIM + d4);

    float acc = 0.0f;

    // structural (dims 0..63)
    {
        const float r1x = rfs.x * (1.0f + tcs.x), r1y = rfs.y * (1.0f + tcs.y);
        const float r1z = rfs.z * (1.0f + tcs.z), r1w = rfs.w * (1.0f + tcs.w);
        const float r2x = ris.x * (1.0f + tcs.x), r2y = ris.y * (1.0f + tcs.y);
        const float r2z = ris.z * (1.0f + tcs.z), r2w = ris.w * (1.0f + tcs.w);
        acc = fmaf(ehh.x * r1x, ett.x, acc);
        acc = fmaf(ehh.y * r1y, ett.y, acc);
        acc = fmaf(ehh.z * r1z, ett.z, acc);
        acc = fmaf(ehh.w * r1w, ett.w, acc);
        acc = fmaf(eht.x * r2x, eth.x, acc);
        acc = fmaf(eht.y * r2y, eth.y, acc);
        acc = fmaf(eht.z * r2z, eth.z, acc);
        acc = fmaf(eht.w * r2w, eth.w, acc);
    }

    // temporal (dims 64..127)
    {
        const float r1x = rft.x * (1.0f + tct.x), r1y = rft.y * (1.0f + tct.y);
        const float r1z = rft.z * (1.0f + tct.z), r1w = rft.w * (1.0f + tct.w);
        const float r2x = rit.x * (1.0f + tct.x), r2y = rit.y * (1.0f + tct.y);
        const float r2z = rit.z * (1.0f + tct.z), r2w = rit.w * (1.0f + tct.w);

        const float h1x = teHh.x + sw.x, h1y = teHh.y + sw.y,
                    h1z = teHh.z + sw.z, h1w = teHh.w + sw.w;
        const float t1x = teTt.x + sw.x, t1y = teTt.y + sw.y,
                    t1z = teTt.z + sw.z, t1w = teTt.w + sw.w;
        const float h2x = teHt.x + sw.x, h2y = teHt.y + sw.y,
                    h2z = teHt.z + sw.z, h2w = teHt.w + sw.w;
        const float t2x = teTh.x + sw.x, t2y = teTh.y + sw.y,
                    t2z = teTh.z + sw.z, t2w = teTh.w + sw.w;

        acc = fmaf(h1x * r1x, t1x, acc);
        acc = fmaf(h1y * r1y, t1y, acc);
        acc = fmaf(h1z * r1z, t1z, acc);
        acc = fmaf(h1w * r1w, t1w, acc);
        acc = fmaf(h2x * r2x, t2x, acc);
        acc = fmaf(h2y * r2y, t2y, acc);
        acc = fmaf(h2z * r2z, t2z, acc);
        acc = fmaf(h2w * r2w, t2w, acc);
    }

    // reduce within 16-lane group (xor offsets stay inside the group)
#pragma unroll
    for (int m = 8; m > 0; m >>= 1)
        acc += __shfl_xor_sync(0xFFFFFFFFu, acc, m);

    if (q == 0)
        out[w] = 0.5f * acc;
}

extern "C" void kernel_launch(void* const* d_in, const int* in_sizes, int n_in,
                              void* d_out, int out_size)
{
    const int*   heads    = (const int*)  d_in[0];
    const int*   rels     = (const int*)  d_in[1];
    const int*   tails    = (const int*)  d_in[2];
    const float* years    = (const float*)d_in[3];
    const float* months   = (const float*)d_in[4];
    const float* days     = (const float*)d_in[5];
    const int*   date_ids = (const int*)  d_in[6];
    const float* ent_h    = (const float*)d_in[7];
    const float* ent_t    = (const float*)d_in[8];
    const float* rel_f    = (const float*)d_in[9];
    const float* rel_i    = (const float*)d_in[10];
    const float* stw      = (const float*)d_in[11];
    const float* rtc      = (const float*)d_in[12];
    const float* amps_h   = (const float*)d_in[13];
    const float* freq_h   = (const float*)d_in[14];
    const float* phi_h    = (const float*)d_in[15];
    const float* amps_t   = (const float*)d_in[16];
    const float* freq_t   = (const float*)d_in[17];
    const float* phi_t    = (const float*)d_in[18];

    zero_kernel<<<(E_CONST + 255) / 256, 256>>>();

    scatter_kernel<<<(2 * B_CONST + 255) / 256, 256>>>(
        heads, tails, years, months, days);

    te_kernel<<<(E_CONST * 32 + 255) / 256, 256>>>(
        amps_h, freq_h, phi_h, amps_t, freq_t, phi_t);

    // 2 samples per warp -> B/2 warps
    score_kernel<<<((B_CONST / 2) * 32 + 255) / 256, 256>>>(
        heads, rels, tails, date_ids,
        ent_h, ent_t, rel_f, rel_i, stw, rtc,
        (float*)d_out);
}

// round 6
// speedup vs baseline: 2.4178x; 1.1993x over previous
#include <cuda_runtime.h>
#include <cuda_fp16.h>
#include <cstddef>

#define B_CONST 262144
#define E_CONST 100000
#define CYCLE 30
#define SDIM 64
#define TDIM 64
#define ROWDIM 128
#define BIN_CAP 96

// ---- static device scratch ----
__device__ int    g_bincnt[E_CONST];
__device__ float4 g_binrec[(size_t)E_CONST * BIN_CAP];  // {y, m, d, item-as-int}
// te scratch in fp16: [sample][vec(role*2+which)][32 half2]
// vec 0 = te_h(head ent), 1 = te_t(head ent), 2 = te_h(tail ent), 3 = te_t(tail ent)
__device__ __half2 g_te[(size_t)B_CONST * 4 * 32];

__device__ __forceinline__ float2 ld2(const float* __restrict__ p) {
    return *reinterpret_cast<const float2*>(p);
}
__device__ __forceinline__ float4 ld4(const float* __restrict__ p) {
    return *reinterpret_cast<const float4*>(p);
}
__device__ __forceinline__ void st_h2_cs(__half2* __restrict__ p, __half2 v) {
    asm volatile("st.global.cs.u32 [%0], %1;"
                 :: "l"(p), "r"(*reinterpret_cast<unsigned*>(&v)) : "memory");
}
// load 2 consecutive half2 (8B) with evict-first policy
__device__ __forceinline__ uint2 ld_u2_cs(const __half2* __restrict__ p) {
    uint2 v;
    asm volatile("ld.global.cs.v2.u32 {%0,%1}, [%2];"
                 : "=r"(v.x), "=r"(v.y) : "l"(p));
    return v;
}

// ---------------- pass 0: zero bin counters ----------------
__global__ void zero_kernel() {
    int i = blockIdx.x * blockDim.x + threadIdx.x;
    if (i < E_CONST) g_bincnt[i] = 0;
}

// ---------------- pass 1: scatter packed items into entity bins ----------------
__global__ void scatter_kernel(const int*   __restrict__ heads,
                               const int*   __restrict__ tails,
                               const float* __restrict__ years,
                               const float* __restrict__ months,
                               const float* __restrict__ days) {
    int i = blockIdx.x * blockDim.x + threadIdx.x;   // item id in [0, 2B)
    if (i >= 2 * B_CONST) return;
    const int s = i >> 1;
    const int e = (i & 1) ? tails[s] : heads[s];
    int pos = atomicAdd(&g_bincnt[e], 1);
    if (pos < BIN_CAP) {
        float4 rec;
        rec.x = years[s];
        rec.y = months[s];
        rec.z = days[s];
        rec.w = __int_as_float(i);
        g_binrec[(size_t)e * BIN_CAP + pos] = rec;
    }
}

// ---------------- pass 2: per-entity gather-once, emit fp16 te per item ----------------
__global__ __launch_bounds__(256)
void te_kernel(const float* __restrict__ amps_h,
               const float* __restrict__ freq_h,
               const float* __restrict__ phi_h,
               const float* __restrict__ amps_t,
               const float* __restrict__ freq_t,
               const float* __restrict__ phi_t)
{
    const int gtid = blockIdx.x * blockDim.x + threadIdx.x;
    const int e    = gtid >> 5;               // one warp per entity bin
    if (e >= E_CONST) return;
    int n = g_bincnt[e];
    if (n <= 0) return;
    if (n > BIN_CAP) n = BIN_CAP;

    const int lane = threadIdx.x & 31;
    const int d2   = lane << 1;

    // gather this entity's 18 unique table rows ONCE into registers
    float2 ah[3], fh[3], ph[3], at[3], ft[3], pt[3];
#pragma unroll
    for (int c = 0; c < 3; ++c) {
        const size_t off = ((size_t)c * E_CONST + (size_t)e) * TDIM + d2;
        ah[c] = ld2(amps_h + off);
        fh[c] = ld2(freq_h + off);
        ph[c] = ld2(phi_h  + off);
        at[c] = ld2(amps_t + off);
        ft[c] = ld2(freq_t + off);
        pt[c] = ld2(phi_t  + off);
    }

    const size_t binbase = (size_t)e * BIN_CAP;
    for (int j = 0; j < n; ++j) {
        const float4 rec = g_binrec[binbase + j];
        const int it   = __float_as_int(rec.w);
        const int s    = it >> 1;
        const int role = it & 1;
        const float tv0 = rec.x, tv1 = rec.y, tv2 = rec.z;

        float hx = 0.f, hy = 0.f, tx = 0.f, ty = 0.f;
        hx = fmaf(ah[0].x, __sinf(fmaf(fh[0].x, tv0, ph[0].x)), hx);
        hy = fmaf(ah[0].y, __sinf(fmaf(fh[0].y, tv0, ph[0].y)), hy);
        tx = fmaf(at[0].x, __sinf(fmaf(ft[0].x, tv0, pt[0].x)), tx);
        ty = fmaf(at[0].y, __sinf(fmaf(ft[0].y, tv0, pt[0].y)), ty);
        hx = fmaf(ah[1].x, __sinf(fmaf(fh[1].x, tv1, ph[1].x)), hx);
        hy = fmaf(ah[1].y, __sinf(fmaf(fh[1].y, tv1, ph[1].y)), hy);
        tx = fmaf(at[1].x, __sinf(fmaf(ft[1].x, tv1, pt[1].x)), tx);
        ty = fmaf(at[1].y, __sinf(fmaf(ft[1].y, tv1, pt[1].y)), ty);
        hx = fmaf(ah[2].x, __sinf(fmaf(fh[2].x, tv2, ph[2].x)), hx);
        hy = fmaf(ah[2].y, __sinf(fmaf(fh[2].y, tv2, ph[2].y)), hy);
        tx = fmaf(at[2].x, __sinf(fmaf(ft[2].x, tv2, pt[2].x)), tx);
        ty = fmaf(at[2].y, __sinf(fmaf(ft[2].y, tv2, pt[2].y)), ty);

        __half2* base = g_te + ((size_t)s * 4 + (size_t)role * 2) * 32 + lane;
        st_h2_cs(base,      __floats2half2_rn(hx, hy));   // te_h(entity)
        st_h2_cs(base + 32, __floats2half2_rn(tx, ty));   // te_t(entity)
    }
}

// ---------------- pass 3: score, 2 samples per warp, float4 lanes ----------------
__global__ __launch_bounds__(256, 6)
void score_kernel(const int*   __restrict__ heads,
                  const int*   __restrict__ rels,
                  const int*   __restrict__ tails,
                  const int*   __restrict__ date_ids,
                  const float* __restrict__ ent_h,
                  const float* __restrict__ ent_t,
                  const float* __restrict__ rel_f,
                  const float* __restrict__ rel_i,
                  const float* __restrict__ stw,
                  const float* __restrict__ rtc,
                  float* __restrict__ out)
{
    const int gtid = blockIdx.x * blockDim.x + threadIdx.x;
    const int w2   = gtid >> 5;                 // warp id: 2 samples per warp
    const int lane = threadIdx.x & 31;
    const int w    = w2 * 2 + (lane >> 4);      // this half-warp's sample
    if (w >= B_CONST) return;
    const int q  = lane & 15;
    const int d4 = q << 2;                       // 4 dims per lane

    const int h  = heads[w];
    const int r  = rels[w];
    const int t  = tails[w];
    const int di = date_ids[w];

    // te scratch: 4 vectors, 8 B (4 halves) per lane each, evict-first
    const __half2* tb = g_te + (size_t)w * 128 + (q << 1);
    const uint2 uHh = ld_u2_cs(tb);
    const uint2 uTh = ld_u2_cs(tb + 32);
    const uint2 uHt = ld_u2_cs(tb + 64);
    const uint2 uTt = ld_u2_cs(tb + 96);

    const float4 sw  = ld4(stw + (size_t)(di / CYCLE) * TDIM + d4);
    const float4 ehh = ld4(ent_h + (size_t)h * SDIM + d4);
    const float4 eht = ld4(ent_h + (size_t)t * SDIM + d4);
    const float4 ett = ld4(ent_t + (size_t)t * SDIM + d4);
    const float4 eth = ld4(ent_t + (size_t)h * SDIM + d4);
    const float4 rfs = ld4(rel_f + (size_t)r * ROWDIM + d4);
    const float4 rft = ld4(rel_f + (size_t)r * ROWDIM + SDIM + d4);
    const float4 ris = ld4(rel_i + (size_t)r * ROWDIM + d4);
    const float4 rit = ld4(rel_i + (size_t)r * ROWDIM + SDIM + d4);
    const float4 tcs = ld4(rtc   + (size_t)di * ROWDIM + d4);
    const float4 tct = ld4(rtc   + (size_t)di * ROWDIM + SDIM + d4);

    float acc = 0.0f;

    // structural (dims 0..63)
    {
        const float r1x = rfs.x * (1.0f + tcs.x), r1y = rfs.y * (1.0f + tcs.y);
        const float r1z = rfs.z * (1.0f + tcs.z), r1w = rfs.w * (1.0f + tcs.w);
        const float r2x = ris.x * (1.0f + tcs.x), r2y = ris.y * (1.0f + tcs.y);
        const float r2z = ris.z * (1.0f + tcs.z), r2w = ris.w * (1.0f + tcs.w);
        acc = fmaf(ehh.x * r1x, ett.x, acc);
        acc = fmaf(ehh.y * r1y, ett.y, acc);
        acc = fmaf(ehh.z * r1z, ett.z, acc);
        acc = fmaf(ehh.w * r1w, ett.w, acc);
        acc = fmaf(eht.x * r2x, eth.x, acc);
        acc = fmaf(eht.y * r2y, eth.y, acc);
        acc = fmaf(eht.z * r2z, eth.z, acc);
        acc = fmaf(eht.w * r2w, eth.w, acc);
    }

    // temporal (dims 64..127)
    {
        const float2 Hh0 = __half22float2(*reinterpret_cast<const __half2*>(&uHh.x));
        const float2 Hh1 = __half22float2(*reinterpret_cast<const __half2*>(&uHh.y));
        const float2 Th0 = __half22float2(*reinterpret_cast<const __half2*>(&uTh.x));
        const float2 Th1 = __half22float2(*reinterpret_cast<const __half2*>(&uTh.y));
        const float2 Ht0 = __half22float2(*reinterpret_cast<const __half2*>(&uHt.x));
        const float2 Ht1 = __half22float2(*reinterpret_cast<const __half2*>(&uHt.y));
        const float2 Tt0 = __half22float2(*reinterpret_cast<const __half2*>(&uTt.x));
        const float2 Tt1 = __half22float2(*reinterpret_cast<const __half2*>(&uTt.y));

        const float r1x = rft.x * (1.0f + tct.x), r1y = rft.y * (1.0f + tct.y);
        const float r1z = rft.z * (1.0f + tct.z), r1w = rft.w * (1.0f + tct.w);
        const float r2x = rit.x * (1.0f + tct.x), r2y = rit.y * (1.0f + tct.y);
        const float r2z = rit.z * (1.0f + tct.z), r2w = rit.w * (1.0f + tct.w);

        // h1 = te_h(head)+sw, t1 = te_t(tail)+sw, h2 = te_h(tail)+sw, t2 = te_t(head)+sw
        acc = fmaf((Hh0.x + sw.x) * r1x, (Tt0.x + sw.x), acc);
        acc = fmaf((Hh0.y + sw.y) * r1y, (Tt0.y + sw.y), acc);
        acc = fmaf((Hh1.x + sw.z) * r1z, (Tt1.x + sw.z), acc);
        acc = fmaf((Hh1.y + sw.w) * r1w, (Tt1.y + sw.w), acc);
        acc = fmaf((Ht0.x + sw.x) * r2x, (Th0.x + sw.x), acc);
        acc = fmaf((Ht0.y + sw.y) * r2y, (Th0.y + sw.y), acc);
        acc = fmaf((Ht1.x + sw.z) * r2z, (Th1.x + sw.z), acc);
        acc = fmaf((Ht1.y + sw.w) * r2w, (Th1.y + sw.w), acc);
    }

    // reduce within 16-lane group
#pragma unroll
    for (int m = 8; m > 0; m >>= 1)
        acc += __shfl_xor_sync(0xFFFFFFFFu, acc, m);

    if (q == 0)
        out[w] = 0.5f * acc;
}

extern "C" void kernel_launch(void* const* d_in, const int* in_sizes, int n_in,
                              void* d_out, int out_size)
{
    const int*   heads    = (const int*)  d_in[0];
    const int*   rels     = (const int*)  d_in[1];
    const int*   tails    = (const int*)  d_in[2];
    const float* years    = (const float*)d_in[3];
    const float* months   = (const float*)d_in[4];
    const float* days     = (const float*)d_in[5];
    const int*   date_ids = (const int*)  d_in[6];
    const float* ent_h    = (const float*)d_in[7];
    const float* ent_t    = (const float*)d_in[8];
    const float* rel_f    = (const float*)d_in[9];
    const float* rel_i    = (const float*)d_in[10];
    const float* stw      = (const float*)d_in[11];
    const float* rtc      = (const float*)d_in[12];
    const float* amps_h   = (const float*)d_in[13];
    const float* freq_h   = (const float*)d_in[14];
    const float* phi_h    = (const float*)d_in[15];
    const float* amps_t   = (const float*)d_in[16];
    const float* freq_t   = (const float*)d_in[17];
    const float* phi_t    = (const float*)d_in[18];

    zero_kernel<<<(E_CONST + 255) / 256, 256>>>();

    scatter_kernel<<<(2 * B_CONST + 255) / 256, 256>>>(
        heads, tails, years, months, days);

    te_kernel<<<(E_CONST * 32 + 255) / 256, 256>>>(
        amps_h, freq_h, phi_h, amps_t, freq_t, phi_t);

    score_kernel<<<((B_CONST / 2) * 32 + 255) / 256, 256>>>(
        heads, rels, tails, date_ids,
        ent_h, ent_t, rel_f, rel_i, stw, rtc,
        (float*)d_out);
}